// round 16
// baseline (speedup 1.0000x reference)
#include <cuda_runtime.h>
#include <cuda_fp16.h>
#include <cstdint>
#include <cstddef>

// ---------------- problem constants ----------------
#define T_TOKENS   8192
#define DM         2048
#define DH         8192
#define NEXP       8
#define CAP        2560
#define NITEMS     (T_TOKENS*2)

// ---------------- device scratch (static) ----------
__device__ __half g_buf [(size_t)NEXP*CAP*DM];
__device__ __half g_h   [(size_t)NEXP*CAP*DH];
__device__ __half g_w1t [(size_t)NEXP*(size_t)DM*DH];
__device__ __half g_w2t [(size_t)NEXP*(size_t)DM*DH];
__device__ int    g_item_e  [NITEMS];
__device__ float  g_item_w  [NITEMS];
__device__ int    g_item_pos[NITEMS];
__device__ int    g_count   [NEXP];
__device__ int    g_slot_t  [(size_t)NEXP*CAP];
__device__ float  g_slot_w  [(size_t)NEXP*CAP];

// ---------------- helpers --------------------------
__device__ __forceinline__ uint32_t smem_u32(const void* p) {
    uint32_t a;
    asm("{ .reg .u64 t; cvta.to.shared.u64 t, %1; cvt.u32.u64 %0, t; }" : "=r"(a) : "l"(p));
    return a;
}
__device__ __forceinline__ void cpasync16(uint32_t dst, const void* src) {
    asm volatile("cp.async.cg.shared.global [%0], [%1], 16;" :: "r"(dst), "l"(src));
}
__device__ __forceinline__ void cp_commit() {
    asm volatile("cp.async.commit_group;" ::: "memory");
}
__device__ __forceinline__ void cp_wait1() {
    asm volatile("cp.async.wait_group 1;" ::: "memory");
}
__device__ __forceinline__ void cp_wait0() {
    asm volatile("cp.async.wait_group 0;" ::: "memory");
}
__device__ __forceinline__ void ldsm4(uint32_t* r, uint32_t addr) {
    asm volatile("ldmatrix.sync.aligned.m8n8.x4.shared.b16 {%0,%1,%2,%3}, [%4];"
        : "=r"(r[0]), "=r"(r[1]), "=r"(r[2]), "=r"(r[3]) : "r"(addr));
}
__device__ __forceinline__ void mma_f16(float* c, const uint32_t* a, const uint32_t* b) {
    asm volatile(
        "mma.sync.aligned.m16n8k16.row.col.f32.f16.f16.f32 "
        "{%0,%1,%2,%3}, {%4,%5,%6,%7}, {%8,%9}, {%0,%1,%2,%3};"
        : "+f"(c[0]), "+f"(c[1]), "+f"(c[2]), "+f"(c[3])
        : "r"(a[0]), "r"(a[1]), "r"(a[2]), "r"(a[3]), "r"(b[0]), "r"(b[1]));
}
__device__ __forceinline__ void red_add_v2(float* addr, float a, float b) {
    asm volatile("red.global.add.v2.f32 [%0], {%1,%2};"
        :: "l"(addr), "f"(a), "f"(b) : "memory");
}

// ---------------- 0) zero output --------------------
__global__ void zero_out_kernel(float* __restrict__ out, int n4) {
    int i = blockIdx.x * blockDim.x + threadIdx.x;
    int stride = gridDim.x * blockDim.x;
    float4 z = {0.f, 0.f, 0.f, 0.f};
    float4* o4 = (float4*)out;
    for (; i < n4; i += stride) o4[i] = z;
}

// ---------------- 1) gating v2: 1 warp = 4 tokens ---
__global__ void gating_kernel(const float* __restrict__ x,
                              const float* __restrict__ gw) {
    int wid = threadIdx.x >> 5, lane = threadIdx.x & 31;
    int t0 = blockIdx.x * 32 + wid * 4;
    const float4* gw4 = (const float4*)gw;
    const float4* xt0 = (const float4*)(x + (size_t)(t0+0) * DM);
    const float4* xt1 = (const float4*)(x + (size_t)(t0+1) * DM);
    const float4* xt2 = (const float4*)(x + (size_t)(t0+2) * DM);
    const float4* xt3 = (const float4*)(x + (size_t)(t0+3) * DM);

    float acc[4][NEXP];
#pragma unroll
    for (int tk = 0; tk < 4; tk++)
#pragma unroll
        for (int e = 0; e < NEXP; e++) acc[tk][e] = 0.f;

    for (int j = lane; j < DM/4; j += 32) {
        float4 g0a = gw4[(4*j+0)*2], g0b = gw4[(4*j+0)*2+1];
        float4 g1a = gw4[(4*j+1)*2], g1b = gw4[(4*j+1)*2+1];
        float4 g2a = gw4[(4*j+2)*2], g2b = gw4[(4*j+2)*2+1];
        float4 g3a = gw4[(4*j+3)*2], g3b = gw4[(4*j+3)*2+1];
        float4 xv[4];
        xv[0] = xt0[j]; xv[1] = xt1[j]; xv[2] = xt2[j]; xv[3] = xt3[j];
#pragma unroll
        for (int tk = 0; tk < 4; tk++) {
            float4 v = xv[tk];
            acc[tk][0] += v.x*g0a.x + v.y*g1a.x + v.z*g2a.x + v.w*g3a.x;
            acc[tk][1] += v.x*g0a.y + v.y*g1a.y + v.z*g2a.y + v.w*g3a.y;
            acc[tk][2] += v.x*g0a.z + v.y*g1a.z + v.z*g2a.z + v.w*g3a.z;
            acc[tk][3] += v.x*g0a.w + v.y*g1a.w + v.z*g2a.w + v.w*g3a.w;
            acc[tk][4] += v.x*g0b.x + v.y*g1b.x + v.z*g2b.x + v.w*g3b.x;
            acc[tk][5] += v.x*g0b.y + v.y*g1b.y + v.z*g2b.y + v.w*g3b.y;
            acc[tk][6] += v.x*g0b.z + v.y*g1b.z + v.z*g2b.z + v.w*g3b.z;
            acc[tk][7] += v.x*g0b.w + v.y*g1b.w + v.z*g2b.w + v.w*g3b.w;
        }
    }
    // warp butterfly reduce (all 32 accumulators)
#pragma unroll
    for (int off = 16; off > 0; off >>= 1) {
#pragma unroll
        for (int tk = 0; tk < 4; tk++)
#pragma unroll
            for (int e = 0; e < NEXP; e++)
                acc[tk][e] += __shfl_xor_sync(0xffffffffu, acc[tk][e], off);
    }
    if (lane == 0) {
#pragma unroll
        for (int tk = 0; tk < 4; tk++) {
            int t = t0 + tk;
            float m = acc[tk][0];
#pragma unroll
            for (int e = 1; e < NEXP; e++) m = fmaxf(m, acc[tk][e]);
            float p[NEXP]; float Z = 0.f;
#pragma unroll
            for (int e = 0; e < NEXP; e++) { p[e] = __expf(acc[tk][e] - m); Z += p[e]; }
            int i0 = 0;
#pragma unroll
            for (int e = 1; e < NEXP; e++) if (p[e] > p[i0]) i0 = e;
            int i1 = (i0 == 0) ? 1 : 0;
#pragma unroll
            for (int e = 0; e < NEXP; e++) if (e != i0 && p[e] > p[i1]) i1 = e;
            float w0 = p[i0] / Z, w1 = p[i1] / Z;
            float s = w0 + w1 + 1e-8f;
            g_item_e[2*t]   = i0;  g_item_e[2*t+1] = i1;
            g_item_w[2*t]   = w0 / s;
            g_item_w[2*t+1] = w1 / s;
        }
    }
}

// ---------------- 2) serial positions (register histograms)
__global__ void position_kernel() {
    __shared__ int cnt[256][NEXP];
    int tid = threadIdx.x;
    int base = tid * (NITEMS / 256);
    const int4* e4 = (const int4*)(g_item_e + base);
    int c[NEXP];
#pragma unroll
    for (int e = 0; e < NEXP; e++) c[e] = 0;
#pragma unroll
    for (int i = 0; i < 16; i++) {
        int4 v = e4[i];
#pragma unroll
        for (int e = 0; e < NEXP; e++) {
            c[e] += (v.x == e) + (v.y == e) + (v.z == e) + (v.w == e);
        }
    }
#pragma unroll
    for (int e = 0; e < NEXP; e++) cnt[tid][e] = c[e];
    __syncthreads();
    if (tid < NEXP) {
        int run = 0;
        for (int j = 0; j < 256; j++) { int cc = cnt[j][tid]; cnt[j][tid] = run; run += cc; }
        g_count[tid] = run < CAP ? run : CAP;
    }
    __syncthreads();
    int run[NEXP];
#pragma unroll
    for (int e = 0; e < NEXP; e++) run[e] = cnt[tid][e];
    int4* p4 = (int4*)(g_item_pos + base);
#pragma unroll
    for (int i = 0; i < 16; i++) {
        int4 v = e4[i];
        int4 o;
        o.x = 0;
#pragma unroll
        for (int e = 0; e < NEXP; e++) { if (v.x == e) o.x = run[e]; }
#pragma unroll
        for (int e = 0; e < NEXP; e++) { run[e] += (v.x == e); }
        o.y = 0;
#pragma unroll
        for (int e = 0; e < NEXP; e++) { if (v.y == e) o.y = run[e]; }
#pragma unroll
        for (int e = 0; e < NEXP; e++) { run[e] += (v.y == e); }
        o.z = 0;
#pragma unroll
        for (int e = 0; e < NEXP; e++) { if (v.z == e) o.z = run[e]; }
#pragma unroll
        for (int e = 0; e < NEXP; e++) { run[e] += (v.z == e); }
        o.w = 0;
#pragma unroll
        for (int e = 0; e < NEXP; e++) { if (v.w == e) o.w = run[e]; }
#pragma unroll
        for (int e = 0; e < NEXP; e++) { run[e] += (v.w == e); }
        p4[i] = o;
    }
}

// ---------------- 3) dispatch (fp16 convert + slot map)
__global__ void dispatch_kernel(const float* __restrict__ x) {
    int i = blockIdx.x;
    int pos = g_item_pos[i];
    if (pos >= CAP) return;
    int e = g_item_e[i];
    int t = i >> 1;
    if (threadIdx.x == 0) {
        g_slot_t[(size_t)e * CAP + pos] = t;
        g_slot_w[(size_t)e * CAP + pos] = g_item_w[i];
    }
    const float4* src = (const float4*)(x + (size_t)t * DM);
    __half2* dst = (__half2*)(g_buf + ((size_t)e * CAP + pos) * DM);
    for (int j = threadIdx.x; j < DM/4; j += blockDim.x) {
        float4 v = src[j];
        dst[2*j]   = __floats2half2_rn(v.x, v.y);
        dst[2*j+1] = __floats2half2_rn(v.z, v.w);
    }
}

// ---------------- 3b) weight transpose + fp16 -------
__global__ void transpose_cvt_half(const float* __restrict__ in,
                                   __half* __restrict__ out, int R, int C) {
    __shared__ float t[64][33];
    int e = blockIdx.z;
    const float* I = in + (size_t)e * R * C;
    __half* O = out + (size_t)e * R * C;
    int c0 = blockIdx.x * 32, r0 = blockIdx.y * 64;
    int tx = threadIdx.x, ty = threadIdx.y;   // block (32,8)
#pragma unroll
    for (int i = 0; i < 8; i++)
        t[ty + 8*i][tx] = I[(size_t)(r0 + ty + 8*i) * C + c0 + tx];
    __syncthreads();
    int tid = ty * 32 + tx;
    int col = tid >> 3;
    int j8  = tid & 7;
    int rbase = j8 * 8;
    __half2 h0 = __floats2half2_rn(t[rbase+0][col], t[rbase+1][col]);
    __half2 h1 = __floats2half2_rn(t[rbase+2][col], t[rbase+3][col]);
    __half2 h2 = __floats2half2_rn(t[rbase+4][col], t[rbase+5][col]);
    __half2 h3 = __floats2half2_rn(t[rbase+6][col], t[rbase+7][col]);
    uint4 pack;
    pack.x = *(uint32_t*)&h0; pack.y = *(uint32_t*)&h1;
    pack.z = *(uint32_t*)&h2; pack.w = *(uint32_t*)&h3;
    *(uint4*)(O + (size_t)(c0 + col) * R + r0 + rbase) = pack;
}

// ---------------- 4) HMMA FP16 GEMM (ldmatrix) ------
#define STGSZ 32768
#define GSMEM (3*STGSZ)   // 96 KB

template<bool RELU, bool SCATTER>
__global__ void __launch_bounds__(256, 2)
moe_gemm(const __half* __restrict__ Aall, const __half* __restrict__ Btall,
         const float* __restrict__ biasall, void* __restrict__ Call,
         int N, int K) {
    int e  = blockIdx.z;
    int bm = blockIdx.y * 128;
    int bn = blockIdx.x * 128;
    if (bm >= g_count[e]) return;

    const __half* A  = Aall  + (size_t)e * CAP * K + (size_t)bm * K;
    const __half* Bt = Btall + (size_t)e * N * K + (size_t)bn * K;
    const float* bias = biasall + (size_t)e * N + bn;

    extern __shared__ char smem[];
    uint32_t sbase = smem_u32(smem);

    int tid = threadIdx.x;
    int wid = tid >> 5, lane = tid & 31;
    int gr = lane >> 2, tg = lane & 3;
    int wm = (wid & 1) * 64, wn = (wid >> 1) * 32;

    int l7 = lane & 7;
    int lh = (lane >> 3) & 1;
    int lq = lane >> 4;

    int aRowL = wm + lh * 8 + l7;
    int bRowL = wn + lq * 8 + l7;

    int a_r = tid >> 1;
    int a_h = tid & 1;
    const __half* aRow = A  + (size_t)a_r * K;
    const __half* bRow = Bt + (size_t)a_r * K;

    float acc[4][4][4];
#pragma unroll
    for (int mi = 0; mi < 4; mi++)
#pragma unroll
        for (int ni = 0; ni < 4; ni++)
#pragma unroll
            for (int r = 0; r < 4; r++) acc[mi][ni][r] = 0.f;

    int NB = K / 64;

    auto stage = [&](int buf, int kbig) {
        uint32_t aDst = sbase + buf * STGSZ + a_r * 128;
        const __half* aSrc = aRow + kbig * 64;
#pragma unroll
        for (int j = 0; j < 4; j++) {
            int c = a_h * 4 + j;
            cpasync16(aDst + (((uint32_t)(c ^ (a_r & 7))) << 4), aSrc + c * 8);
        }
        uint32_t bDst = sbase + buf * STGSZ + 16384 + a_r * 128;
        const __half* bSrc = bRow + kbig * 64;
#pragma unroll
        for (int j = 0; j < 4; j++) {
            int c = a_h * 4 + j;
            cpasync16(bDst + (((uint32_t)(c ^ (a_r & 7))) << 4), bSrc + c * 8);
        }
    };

    stage(0, 0); cp_commit();
    stage(1, 1); cp_commit();

    int buf = 0;
    for (int big = 0; big < NB; big++) {
        if (big + 2 < NB) cp_wait1(); else cp_wait0();
        __syncthreads();

        if (big + 2 < NB) {
            int nbuf = buf + 2; if (nbuf >= 3) nbuf -= 3;
            stage(nbuf, big + 2);
            cp_commit();
        }

        uint32_t sA = sbase + buf * STGSZ;
        uint32_t sB = sA + 16384;
#pragma unroll
        for (int k16 = 0; k16 < 64; k16 += 16) {
            int ch0 = k16 >> 3;
            uint32_t a[4][4];
#pragma unroll
            for (int mi = 0; mi < 4; mi++) {
                int row = aRowL + mi * 16;
                uint32_t addr = sA + row * 128 + (((uint32_t)((ch0 + lq) ^ (row & 7))) << 4);
                ldsm4(a[mi], addr);
            }
            uint32_t b[4][2];
#pragma unroll
            for (int p = 0; p < 2; p++) {
                int n = bRowL + p * 16;
                uint32_t addr = sB + n * 128 + (((uint32_t)((ch0 + lh) ^ (n & 7))) << 4);
                uint32_t t4[4];
                ldsm4(t4, addr);
                b[2*p][0]   = t4[0];
                b[2*p][1]   = t4[1];
                b[2*p+1][0] = t4[2];
                b[2*p+1][1] = t4[3];
            }
#pragma unroll
            for (int mi = 0; mi < 4; mi++)
#pragma unroll
                for (int ni = 0; ni < 4; ni++)
                    mma_f16(acc[mi][ni], a[mi], b[ni]);
        }

        buf++; if (buf >= 3) buf = 0;
    }

    // epilogue
#pragma unroll
    for (int mi = 0; mi < 4; mi++) {
        int row0 = bm + wm + mi * 16 + gr;
        int row1 = row0 + 8;
        if (SCATTER) {
            int   t0 = g_slot_t[(size_t)e * CAP + row0];
            float s0 = g_slot_w[(size_t)e * CAP + row0];
            int   t1 = g_slot_t[(size_t)e * CAP + row1];
            float s1 = g_slot_w[(size_t)e * CAP + row1];
            float* out = (float*)Call;
#pragma unroll
            for (int ni = 0; ni < 4; ni++) {
                int col = wn + ni * 8 + 2 * tg;
                float2 b2 = *(const float2*)(bias + col);
                float v0 = (acc[mi][ni][0] + b2.x) * s0;
                float v1 = (acc[mi][ni][1] + b2.y) * s0;
                float v2 = (acc[mi][ni][2] + b2.x) * s1;
                float v3 = (acc[mi][ni][3] + b2.y) * s1;
                red_add_v2(out + (size_t)t0 * DM + bn + col, v0, v1);
                red_add_v2(out + (size_t)t1 * DM + bn + col, v2, v3);
            }
        } else {
#pragma unroll
            for (int ni = 0; ni < 4; ni++) {
                int col = wn + ni * 8 + 2 * tg;
                float2 b2 = *(const float2*)(bias + col);
                float v0 = acc[mi][ni][0] + b2.x;
                float v1 = acc[mi][ni][1] + b2.y;
                float v2 = acc[mi][ni][2] + b2.x;
                float v3 = acc[mi][ni][3] + b2.y;
                if (RELU) {
                    v0 = fmaxf(v0, 0.f); v1 = fmaxf(v1, 0.f);
                    v2 = fmaxf(v2, 0.f); v3 = fmaxf(v3, 0.f);
                }
                __half* Ch = (__half*)Call + (size_t)e * CAP * N;
                *(__half2*)(Ch + (size_t)row0 * N + bn + col) = __floats2half2_rn(v0, v1);
                *(__half2*)(Ch + (size_t)row1 * N + bn + col) = __floats2half2_rn(v2, v3);
            }
        }
    }
}

// ---------------- launcher --------------------------
extern "C" void kernel_launch(void* const* d_in, const int* in_sizes, int n_in,
                              void* d_out, int out_size) {
    const float* x  = (const float*)d_in[0];
    const float* gw = (const float*)d_in[1];
    const float* w1 = (const float*)d_in[2];
    const float* b1 = (const float*)d_in[3];
    const float* w2 = (const float*)d_in[4];
    const float* b2 = (const float*)d_in[5];
    float* out = (float*)d_out;

    void *pbuf, *ph, *pw1t, *pw2t;
    cudaGetSymbolAddress(&pbuf,  g_buf);
    cudaGetSymbolAddress(&ph,    g_h);
    cudaGetSymbolAddress(&pw1t,  g_w1t);
    cudaGetSymbolAddress(&pw2t,  g_w2t);

    cudaFuncSetAttribute(moe_gemm<true,  false>, cudaFuncAttributeMaxDynamicSharedMemorySize, GSMEM);
    cudaFuncSetAttribute(moe_gemm<false, true >, cudaFuncAttributeMaxDynamicSharedMemorySize, GSMEM);

    static cudaStream_t s_side = nullptr;
    static cudaEvent_t  s_fork = nullptr, s_ev1 = nullptr, s_ev2 = nullptr;
    if (!s_side) {
        cudaStreamCreateWithFlags(&s_side, cudaStreamNonBlocking);
        cudaEventCreateWithFlags(&s_fork, cudaEventDisableTiming);
        cudaEventCreateWithFlags(&s_ev1,  cudaEventDisableTiming);
        cudaEventCreateWithFlags(&s_ev2,  cudaEventDisableTiming);
    }

    // side stream: w1 transpose -> ev1 -> w2 transpose -> ev2
    cudaEventRecord(s_fork, 0);
    cudaStreamWaitEvent(s_side, s_fork, 0);
    transpose_cvt_half<<<dim3(DH/32, DM/64, NEXP), dim3(32, 8), 0, s_side>>>(w1, (__half*)pw1t, DM, DH);
    cudaEventRecord(s_ev1, s_side);
    transpose_cvt_half<<<dim3(DM/32, DH/64, NEXP), dim3(32, 8), 0, s_side>>>(w2, (__half*)pw2t, DH, DM);
    cudaEventRecord(s_ev2, s_side);

    // main stream: zero output + token chain
    zero_out_kernel<<<2048, 256>>>(out, T_TOKENS * DM / 4);
    gating_kernel<<<T_TOKENS/32, 256>>>(x, gw);
    position_kernel<<<1, 256>>>();
    dispatch_kernel<<<NITEMS, 128>>>(x);

    // GEMM1 needs only w1t
    cudaStreamWaitEvent(0, s_ev1, 0);
    moe_gemm<true,  false><<<dim3(DH/128, CAP/128, NEXP), 256, GSMEM>>>(
        (const __half*)pbuf, (const __half*)pw1t, b1, ph, DH, DM);

    // GEMM2 needs w2t (transpose hidden under GEMM1)
    cudaStreamWaitEvent(0, s_ev2, 0);
    moe_gemm<false, true ><<<dim3(DM/128, CAP/128, NEXP), 256, GSMEM>>>(
        (const __half*)ph, (const __half*)pw2t, b2, out, DM, DH);
}

// round 17
// speedup vs baseline: 1.5440x; 1.5440x over previous
#include <cuda_runtime.h>
#include <cuda_fp16.h>
#include <cstdint>
#include <cstddef>

// ---------------- problem constants ----------------
#define T_TOKENS   8192
#define DM         2048
#define DH         8192
#define NEXP       8
#define CAP        2560
#define NITEMS     (T_TOKENS*2)

// ---------------- device scratch (static) ----------
__device__ __half g_buf [(size_t)NEXP*CAP*DM];
__device__ __half g_h   [(size_t)NEXP*CAP*DH];
__device__ __half g_w1t [(size_t)NEXP*(size_t)DM*DH];
__device__ __half g_w2t [(size_t)NEXP*(size_t)DM*DH];
__device__ int    g_item_e  [NITEMS];
__device__ float  g_item_w  [NITEMS];
__device__ int    g_item_pos[NITEMS];
__device__ int    g_count   [NEXP];
__device__ int    g_slot_t  [(size_t)NEXP*CAP];
__device__ float  g_slot_w  [(size_t)NEXP*CAP];

// ---------------- helpers --------------------------
__device__ __forceinline__ uint32_t smem_u32(const void* p) {
    uint32_t a;
    asm("{ .reg .u64 t; cvta.to.shared.u64 t, %1; cvt.u32.u64 %0, t; }" : "=r"(a) : "l"(p));
    return a;
}
__device__ __forceinline__ void cpasync16(uint32_t dst, const void* src) {
    asm volatile("cp.async.cg.shared.global [%0], [%1], 16;" :: "r"(dst), "l"(src));
}
__device__ __forceinline__ void cp_commit() {
    asm volatile("cp.async.commit_group;" ::: "memory");
}
__device__ __forceinline__ void cp_wait1() {
    asm volatile("cp.async.wait_group 1;" ::: "memory");
}
__device__ __forceinline__ void cp_wait0() {
    asm volatile("cp.async.wait_group 0;" ::: "memory");
}
__device__ __forceinline__ void ldsm4(uint32_t* r, uint32_t addr) {
    asm volatile("ldmatrix.sync.aligned.m8n8.x4.shared.b16 {%0,%1,%2,%3}, [%4];"
        : "=r"(r[0]), "=r"(r[1]), "=r"(r[2]), "=r"(r[3]) : "r"(addr));
}
__device__ __forceinline__ void mma_f16(float* c, const uint32_t* a, const uint32_t* b) {
    asm volatile(
        "mma.sync.aligned.m16n8k16.row.col.f32.f16.f16.f32 "
        "{%0,%1,%2,%3}, {%4,%5,%6,%7}, {%8,%9}, {%0,%1,%2,%3};"
        : "+f"(c[0]), "+f"(c[1]), "+f"(c[2]), "+f"(c[3])
        : "r"(a[0]), "r"(a[1]), "r"(a[2]), "r"(a[3]), "r"(b[0]), "r"(b[1]));
}
__device__ __forceinline__ void red_add_v2(float* addr, float a, float b) {
    asm volatile("red.global.add.v2.f32 [%0], {%1,%2};"
        :: "l"(addr), "f"(a), "f"(b) : "memory");
}

// ---------------- 0) zero output --------------------
__global__ void zero_out_kernel(float* __restrict__ out, int n4) {
    int i = blockIdx.x * blockDim.x + threadIdx.x;
    int stride = gridDim.x * blockDim.x;
    float4 z = {0.f, 0.f, 0.f, 0.f};
    float4* o4 = (float4*)out;
    for (; i < n4; i += stride) o4[i] = z;
}

// ---------------- 1) gating: 1 warp = 4 tokens ------
__global__ void gating_kernel(const float* __restrict__ x,
                              const float* __restrict__ gw) {
    int wid = threadIdx.x >> 5, lane = threadIdx.x & 31;
    int t0 = blockIdx.x * 32 + wid * 4;
    const float4* gw4 = (const float4*)gw;
    const float4* xt0 = (const float4*)(x + (size_t)(t0+0) * DM);
    const float4* xt1 = (const float4*)(x + (size_t)(t0+1) * DM);
    const float4* xt2 = (const float4*)(x + (size_t)(t0+2) * DM);
    const float4* xt3 = (const float4*)(x + (size_t)(t0+3) * DM);

    float acc[4][NEXP];
#pragma unroll
    for (int tk = 0; tk < 4; tk++)
#pragma unroll
        for (int e = 0; e < NEXP; e++) acc[tk][e] = 0.f;

    for (int j = lane; j < DM/4; j += 32) {
        float4 g0a = gw4[(4*j+0)*2], g0b = gw4[(4*j+0)*2+1];
        float4 g1a = gw4[(4*j+1)*2], g1b = gw4[(4*j+1)*2+1];
        float4 g2a = gw4[(4*j+2)*2], g2b = gw4[(4*j+2)*2+1];
        float4 g3a = gw4[(4*j+3)*2], g3b = gw4[(4*j+3)*2+1];
        float4 xv[4];
        xv[0] = xt0[j]; xv[1] = xt1[j]; xv[2] = xt2[j]; xv[3] = xt3[j];
#pragma unroll
        for (int tk = 0; tk < 4; tk++) {
            float4 v = xv[tk];
            acc[tk][0] += v.x*g0a.x + v.y*g1a.x + v.z*g2a.x + v.w*g3a.x;
            acc[tk][1] += v.x*g0a.y + v.y*g1a.y + v.z*g2a.y + v.w*g3a.y;
            acc[tk][2] += v.x*g0a.z + v.y*g1a.z + v.z*g2a.z + v.w*g3a.z;
            acc[tk][3] += v.x*g0a.w + v.y*g1a.w + v.z*g2a.w + v.w*g3a.w;
            acc[tk][4] += v.x*g0b.x + v.y*g1b.x + v.z*g2b.x + v.w*g3b.x;
            acc[tk][5] += v.x*g0b.y + v.y*g1b.y + v.z*g2b.y + v.w*g3b.y;
            acc[tk][6] += v.x*g0b.z + v.y*g1b.z + v.z*g2b.z + v.w*g3b.z;
            acc[tk][7] += v.x*g0b.w + v.y*g1b.w + v.z*g2b.w + v.w*g3b.w;
        }
    }
#pragma unroll
    for (int off = 16; off > 0; off >>= 1) {
#pragma unroll
        for (int tk = 0; tk < 4; tk++)
#pragma unroll
            for (int e = 0; e < NEXP; e++)
                acc[tk][e] += __shfl_xor_sync(0xffffffffu, acc[tk][e], off);
    }
    if (lane == 0) {
#pragma unroll
        for (int tk = 0; tk < 4; tk++) {
            int t = t0 + tk;
            float m = acc[tk][0];
#pragma unroll
            for (int e = 1; e < NEXP; e++) m = fmaxf(m, acc[tk][e]);
            float p[NEXP]; float Z = 0.f;
#pragma unroll
            for (int e = 0; e < NEXP; e++) { p[e] = __expf(acc[tk][e] - m); Z += p[e]; }
            int i0 = 0;
#pragma unroll
            for (int e = 1; e < NEXP; e++) if (p[e] > p[i0]) i0 = e;
            int i1 = (i0 == 0) ? 1 : 0;
#pragma unroll
            for (int e = 0; e < NEXP; e++) if (e != i0 && p[e] > p[i1]) i1 = e;
            float w0 = p[i0] / Z, w1 = p[i1] / Z;
            float s = w0 + w1 + 1e-8f;
            g_item_e[2*t]   = i0;  g_item_e[2*t+1] = i1;
            g_item_w[2*t]   = w0 / s;
            g_item_w[2*t+1] = w1 / s;
        }
    }
}

// ---------------- 2) serial positions (register histograms)
__global__ void position_kernel() {
    __shared__ int cnt[256][NEXP];
    int tid = threadIdx.x;
    int base = tid * (NITEMS / 256);
    const int4* e4 = (const int4*)(g_item_e + base);
    int c[NEXP];
#pragma unroll
    for (int e = 0; e < NEXP; e++) c[e] = 0;
#pragma unroll
    for (int i = 0; i < 16; i++) {
        int4 v = e4[i];
#pragma unroll
        for (int e = 0; e < NEXP; e++) {
            c[e] += (v.x == e) + (v.y == e) + (v.z == e) + (v.w == e);
        }
    }
#pragma unroll
    for (int e = 0; e < NEXP; e++) cnt[tid][e] = c[e];
    __syncthreads();
    if (tid < NEXP) {
        int run = 0;
        for (int j = 0; j < 256; j++) { int cc = cnt[j][tid]; cnt[j][tid] = run; run += cc; }
        g_count[tid] = run < CAP ? run : CAP;
    }
    __syncthreads();
    int run[NEXP];
#pragma unroll
    for (int e = 0; e < NEXP; e++) run[e] = cnt[tid][e];
    int4* p4 = (int4*)(g_item_pos + base);
#pragma unroll
    for (int i = 0; i < 16; i++) {
        int4 v = e4[i];
        int4 o;
        o.x = 0;
#pragma unroll
        for (int e = 0; e < NEXP; e++) { if (v.x == e) o.x = run[e]; }
#pragma unroll
        for (int e = 0; e < NEXP; e++) { run[e] += (v.x == e); }
        o.y = 0;
#pragma unroll
        for (int e = 0; e < NEXP; e++) { if (v.y == e) o.y = run[e]; }
#pragma unroll
        for (int e = 0; e < NEXP; e++) { run[e] += (v.y == e); }
        o.z = 0;
#pragma unroll
        for (int e = 0; e < NEXP; e++) { if (v.z == e) o.z = run[e]; }
#pragma unroll
        for (int e = 0; e < NEXP; e++) { run[e] += (v.z == e); }
        o.w = 0;
#pragma unroll
        for (int e = 0; e < NEXP; e++) { if (v.w == e) o.w = run[e]; }
#pragma unroll
        for (int e = 0; e < NEXP; e++) { run[e] += (v.w == e); }
        p4[i] = o;
    }
}

// ---------------- 3) dispatch (fp16 convert + slot map)
__global__ void dispatch_kernel(const float* __restrict__ x) {
    int i = blockIdx.x;
    int pos = g_item_pos[i];
    if (pos >= CAP) return;
    int e = g_item_e[i];
    int t = i >> 1;
    if (threadIdx.x == 0) {
        g_slot_t[(size_t)e * CAP + pos] = t;
        g_slot_w[(size_t)e * CAP + pos] = g_item_w[i];
    }
    const float4* src = (const float4*)(x + (size_t)t * DM);
    __half2* dst = (__half2*)(g_buf + ((size_t)e * CAP + pos) * DM);
    for (int j = threadIdx.x; j < DM/4; j += blockDim.x) {
        float4 v = src[j];
        dst[2*j]   = __floats2half2_rn(v.x, v.y);
        dst[2*j+1] = __floats2half2_rn(v.z, v.w);
    }
}

// ---------------- 3b) weight transpose + fp16 -------
__global__ void transpose_cvt_half(const float* __restrict__ in,
                                   __half* __restrict__ out, int R, int C) {
    __shared__ float t[64][33];
    int e = blockIdx.z;
    const float* I = in + (size_t)e * R * C;
    __half* O = out + (size_t)e * R * C;
    int c0 = blockIdx.x * 32, r0 = blockIdx.y * 64;
    int tx = threadIdx.x, ty = threadIdx.y;   // block (32,8)
#pragma unroll
    for (int i = 0; i < 8; i++)
        t[ty + 8*i][tx] = I[(size_t)(r0 + ty + 8*i) * C + c0 + tx];
    __syncthreads();
    int tid = ty * 32 + tx;
    int col = tid >> 3;
    int j8  = tid & 7;
    int rbase = j8 * 8;
    __half2 h0 = __floats2half2_rn(t[rbase+0][col], t[rbase+1][col]);
    __half2 h1 = __floats2half2_rn(t[rbase+2][col], t[rbase+3][col]);
    __half2 h2 = __floats2half2_rn(t[rbase+4][col], t[rbase+5][col]);
    __half2 h3 = __floats2half2_rn(t[rbase+6][col], t[rbase+7][col]);
    uint4 pack;
    pack.x = *(uint32_t*)&h0; pack.y = *(uint32_t*)&h1;
    pack.z = *(uint32_t*)&h2; pack.w = *(uint32_t*)&h3;
    *(uint4*)(O + (size_t)(c0 + col) * R + r0 + rbase) = pack;
}

// ---------------- 4) HMMA FP16 GEMM (ldmatrix) ------
#define STGSZ 32768
#define GSMEM (3*STGSZ)   // 96 KB

template<bool RELU, bool SCATTER>
__global__ void __launch_bounds__(256, 2)
moe_gemm(const __half* __restrict__ Aall, const __half* __restrict__ Btall,
         const float* __restrict__ biasall, void* __restrict__ Call,
         int N, int K) {
    int e  = blockIdx.z;
    int bm = blockIdx.y * 128;
    int bn = blockIdx.x * 128;
    if (bm >= g_count[e]) return;

    const __half* A  = Aall  + (size_t)e * CAP * K + (size_t)bm * K;
    const __half* Bt = Btall + (size_t)e * N * K + (size_t)bn * K;
    const float* bias = biasall + (size_t)e * N + bn;

    extern __shared__ char smem[];
    uint32_t sbase = smem_u32(smem);

    int tid = threadIdx.x;
    int wid = tid >> 5, lane = tid & 31;
    int gr = lane >> 2, tg = lane & 3;
    int wm = (wid & 1) * 64, wn = (wid >> 1) * 32;

    int l7 = lane & 7;
    int lh = (lane >> 3) & 1;
    int lq = lane >> 4;

    int aRowL = wm + lh * 8 + l7;
    int bRowL = wn + lq * 8 + l7;

    int a_r = tid >> 1;
    int a_h = tid & 1;
    const __half* aRow = A  + (size_t)a_r * K;
    const __half* bRow = Bt + (size_t)a_r * K;

    float acc[4][4][4];
#pragma unroll
    for (int mi = 0; mi < 4; mi++)
#pragma unroll
        for (int ni = 0; ni < 4; ni++)
#pragma unroll
            for (int r = 0; r < 4; r++) acc[mi][ni][r] = 0.f;

    int NB = K / 64;

    auto stage = [&](int buf, int kbig) {
        uint32_t aDst = sbase + buf * STGSZ + a_r * 128;
        const __half* aSrc = aRow + kbig * 64;
#pragma unroll
        for (int j = 0; j < 4; j++) {
            int c = a_h * 4 + j;
            cpasync16(aDst + (((uint32_t)(c ^ (a_r & 7))) << 4), aSrc + c * 8);
        }
        uint32_t bDst = sbase + buf * STGSZ + 16384 + a_r * 128;
        const __half* bSrc = bRow + kbig * 64;
#pragma unroll
        for (int j = 0; j < 4; j++) {
            int c = a_h * 4 + j;
            cpasync16(bDst + (((uint32_t)(c ^ (a_r & 7))) << 4), bSrc + c * 8);
        }
    };

    stage(0, 0); cp_commit();
    stage(1, 1); cp_commit();

    int buf = 0;
    for (int big = 0; big < NB; big++) {
        if (big + 2 < NB) cp_wait1(); else cp_wait0();
        __syncthreads();

        if (big + 2 < NB) {
            int nbuf = buf + 2; if (nbuf >= 3) nbuf -= 3;
            stage(nbuf, big + 2);
            cp_commit();
        }

        uint32_t sA = sbase + buf * STGSZ;
        uint32_t sB = sA + 16384;
#pragma unroll
        for (int k16 = 0; k16 < 64; k16 += 16) {
            int ch0 = k16 >> 3;
            uint32_t a[4][4];
#pragma unroll
            for (int mi = 0; mi < 4; mi++) {
                int row = aRowL + mi * 16;
                uint32_t addr = sA + row * 128 + (((uint32_t)((ch0 + lq) ^ (row & 7))) << 4);
                ldsm4(a[mi], addr);
            }
            uint32_t b[4][2];
#pragma unroll
            for (int p = 0; p < 2; p++) {
                int n = bRowL + p * 16;
                uint32_t addr = sB + n * 128 + (((uint32_t)((ch0 + lh) ^ (n & 7))) << 4);
                uint32_t t4[4];
                ldsm4(t4, addr);
                b[2*p][0]   = t4[0];
                b[2*p][1]   = t4[1];
                b[2*p+1][0] = t4[2];
                b[2*p+1][1] = t4[3];
            }
#pragma unroll
            for (int mi = 0; mi < 4; mi++)
#pragma unroll
                for (int ni = 0; ni < 4; ni++)
                    mma_f16(acc[mi][ni], a[mi], b[ni]);
        }

        buf++; if (buf >= 3) buf = 0;
    }

    // epilogue
#pragma unroll
    for (int mi = 0; mi < 4; mi++) {
        int row0 = bm + wm + mi * 16 + gr;
        int row1 = row0 + 8;
        if (SCATTER) {
            int   t0 = g_slot_t[(size_t)e * CAP + row0];
            float s0 = g_slot_w[(size_t)e * CAP + row0];
            int   t1 = g_slot_t[(size_t)e * CAP + row1];
            float s1 = g_slot_w[(size_t)e * CAP + row1];
            float* out = (float*)Call;
#pragma unroll
            for (int ni = 0; ni < 4; ni++) {
                int col = wn + ni * 8 + 2 * tg;
                float2 b2 = *(const float2*)(bias + col);
                float v0 = (acc[mi][ni][0] + b2.x) * s0;
                float v1 = (acc[mi][ni][1] + b2.y) * s0;
                float v2 = (acc[mi][ni][2] + b2.x) * s1;
                float v3 = (acc[mi][ni][3] + b2.y) * s1;
                red_add_v2(out + (size_t)t0 * DM + bn + col, v0, v1);
                red_add_v2(out + (size_t)t1 * DM + bn + col, v2, v3);
            }
        } else {
#pragma unroll
            for (int ni = 0; ni < 4; ni++) {
                int col = wn + ni * 8 + 2 * tg;
                float2 b2 = *(const float2*)(bias + col);
                float v0 = acc[mi][ni][0] + b2.x;
                float v1 = acc[mi][ni][1] + b2.y;
                float v2 = acc[mi][ni][2] + b2.x;
                float v3 = acc[mi][ni][3] + b2.y;
                if (RELU) {
                    v0 = fmaxf(v0, 0.f); v1 = fmaxf(v1, 0.f);
                    v2 = fmaxf(v2, 0.f); v3 = fmaxf(v3, 0.f);
                }
                __half* Ch = (__half*)Call + (size_t)e * CAP * N;
                *(__half2*)(Ch + (size_t)row0 * N + bn + col) = __floats2half2_rn(v0, v1);
                *(__half2*)(Ch + (size_t)row1 * N + bn + col) = __floats2half2_rn(v2, v3);
            }
        }
    }
}

// ---------------- launcher --------------------------
extern "C" void kernel_launch(void* const* d_in, const int* in_sizes, int n_in,
                              void* d_out, int out_size) {
    const float* x  = (const float*)d_in[0];
    const float* gw = (const float*)d_in[1];
    const float* w1 = (const float*)d_in[2];
    const float* b1 = (const float*)d_in[3];
    const float* w2 = (const float*)d_in[4];
    const float* b2 = (const float*)d_in[5];
    float* out = (float*)d_out;

    void *pbuf, *ph, *pw1t, *pw2t;
    cudaGetSymbolAddress(&pbuf,  g_buf);
    cudaGetSymbolAddress(&ph,    g_h);
    cudaGetSymbolAddress(&pw1t,  g_w1t);
    cudaGetSymbolAddress(&pw2t,  g_w2t);

    cudaFuncSetAttribute(moe_gemm<true,  false>, cudaFuncAttributeMaxDynamicSharedMemorySize, GSMEM);
    cudaFuncSetAttribute(moe_gemm<false, true >, cudaFuncAttributeMaxDynamicSharedMemorySize, GSMEM);

    static cudaStream_t s_side = nullptr;
    static cudaEvent_t  s_fork = nullptr, s_join = nullptr;
    if (!s_side) {
        cudaStreamCreateWithFlags(&s_side, cudaStreamNonBlocking);
        cudaEventCreateWithFlags(&s_fork, cudaEventDisableTiming);
        cudaEventCreateWithFlags(&s_join, cudaEventDisableTiming);
    }

    // side stream: BOTH weight transposes complete before any GEMM
    // (R16 showed overlapping a bulk DRAM kernel with GEMM1 is disastrous)
    cudaEventRecord(s_fork, 0);
    cudaStreamWaitEvent(s_side, s_fork, 0);
    transpose_cvt_half<<<dim3(DH/32, DM/64, NEXP), dim3(32, 8), 0, s_side>>>(w1, (__half*)pw1t, DM, DH);
    transpose_cvt_half<<<dim3(DM/32, DH/64, NEXP), dim3(32, 8), 0, s_side>>>(w2, (__half*)pw2t, DH, DM);
    cudaEventRecord(s_join, s_side);

    // main stream: zero output + token chain (overlaps transposes)
    zero_out_kernel<<<2048, 256>>>(out, T_TOKENS * DM / 4);
    gating_kernel<<<T_TOKENS/32, 256>>>(x, gw);
    position_kernel<<<1, 256>>>();
    dispatch_kernel<<<NITEMS, 128>>>(x);

    cudaStreamWaitEvent(0, s_join, 0);

    // h = relu(buf @ w1 + b1): N=DH, K=DM
    moe_gemm<true,  false><<<dim3(DH/128, CAP/128, NEXP), 256, GSMEM>>>(
        (const __half*)pbuf, (const __half*)pw1t, b1, ph, DH, DM);
    // out += scatter( (h @ w2 + b2) * w_slot ): N=DM, K=DH
    moe_gemm<false, true ><<<dim3(DM/128, CAP/128, NEXP), 256, GSMEM>>>(
        (const __half*)ph, (const __half*)pw2t, b2, out, DM, DH);
}